// round 11
// baseline (speedup 1.0000x reference)
#include <cuda_runtime.h>
#include <cuda_bf16.h>
#include <cstdint>

// EdgeConvE: B=4, V=1024, C=64, E=16, K=32, OUT=128, NODES=4096, EDGES=131072
// src = repeat(arange(4096), 32) (structural) => segment n = edges [n*32,(n+1)*32)
// dst & 1023 = local neighbor (block-diagonal graphs).
//
// Algebra: feat@W = x_s@(W1-W2) + x_d@W2 + e@W3
//   A[n] = x_n@(W1-W2)+b ; C[n] = x_n@W2
//   out[n][j] = max(0, A[n][j] + max_k( C[dst_k][j] + e_k . W3[:,j] ))

#define NODES 4096
#define VDIM  1024
#define CDIM  64
#define EDIM  16
#define KNBR  32
#define OUTD  128
#define EPAD  20     // E smem row stride in floats (bank-conflict-free)

__device__ float g_A[NODES * OUTD];
__device__ float g_C[NODES * OUTD];

// ---------------- f32x2 helpers ----------------
__device__ __forceinline__ uint64_t pack_f32x2(float lo, float hi) {
    uint64_t r;
    asm("mov.b64 %0, {%1, %2};" : "=l"(r) : "f"(lo), "f"(hi));
    return r;
}
__device__ __forceinline__ void unpack_f32x2(float& lo, float& hi, uint64_t v) {
    asm("mov.b64 {%0, %1}, %2;" : "=f"(lo), "=f"(hi) : "l"(v));
}
__device__ __forceinline__ uint64_t fma_f32x2(uint64_t a, uint64_t b, uint64_t c) {
    uint64_t d;
    asm("fma.rn.f32x2 %0, %1, %2, %3;" : "=l"(d) : "l"(a), "l"(b), "l"(c));
    return d;
}
__device__ __forceinline__ void lds_v2_u64(uint64_t& a, uint64_t& b, uint32_t addr) {
    asm("ld.shared.v2.u64 {%0, %1}, [%2];" : "=l"(a), "=l"(b) : "r"(addr));
}
__device__ __forceinline__ uint64_t lds_u64(uint32_t addr) {
    uint64_t a;
    asm("ld.shared.u64 %0, [%1];" : "=l"(a) : "r"(addr));
    return a;
}
__device__ __forceinline__ uint32_t smem_u32(const void* p) {
    return (uint32_t)__cvta_generic_to_shared(p);
}
__device__ __forceinline__ void cp_async16(uint32_t s, const void* g) {
    asm volatile("cp.async.cg.shared.global [%0], [%1], 16;" :: "r"(s), "l"(g));
}

// ---------------------------------------------------------------------------
// Kernel 1: per-node linear tables (f32x2-packed over node pairs). grid 1024.
// ---------------------------------------------------------------------------
#define NT_NODES 4
__global__ void __launch_bounds__(128) node_tables_kernel(
    const float* __restrict__ x, const float* __restrict__ W,
    const float* __restrict__ bias)
{
    __shared__ float xs[CDIM][NT_NODES];
    const int j  = threadIdx.x;
    const int n0 = blockIdx.x * NT_NODES;

    for (int it = 0; it < NT_NODES * CDIM / 128; it++) {
        int idx = j + it * 128;
        xs[idx & 63][idx >> 6] = x[n0 * CDIM + idx];
    }
    __syncthreads();

    const float bj = bias[j];
    uint64_t accA[NT_NODES / 2], accC[NT_NODES / 2];
#pragma unroll
    for (int p = 0; p < NT_NODES / 2; p++) {
        accA[p] = pack_f32x2(bj, bj);
        accC[p] = pack_f32x2(0.0f, 0.0f);
    }
    const uint32_t xs_base = smem_u32(&xs[0][0]);

#pragma unroll 8
    for (int c = 0; c < CDIM; c++) {
        const float w1 = W[c * OUTD + j];
        const float w2 = W[(CDIM + c) * OUTD + j];
        const uint64_t wd2 = pack_f32x2(w1 - w2, w1 - w2);
        const uint64_t w22 = pack_f32x2(w2, w2);
        const uint32_t rowa = xs_base + c * (NT_NODES * 4);
#pragma unroll
        for (int p = 0; p < NT_NODES / 2; p++) {
            uint64_t xv2 = lds_u64(rowa + p * 8);
            accA[p] = fma_f32x2(xv2, wd2, accA[p]);
            accC[p] = fma_f32x2(xv2, w22, accC[p]);
        }
    }
#pragma unroll
    for (int p = 0; p < NT_NODES / 2; p++) {
        float a0, a1, c0, c1;
        unpack_f32x2(a0, a1, accA[p]);
        unpack_f32x2(c0, c1, accC[p]);
        g_A[(n0 + 2 * p) * OUTD + j]     = a0;
        g_A[(n0 + 2 * p + 1) * OUTD + j] = a1;
        g_C[(n0 + 2 * p) * OUTD + j]     = c0;
        g_C[(n0 + 2 * p + 1) * OUTD + j] = c1;
    }
}

// ---------------------------------------------------------------------------
// Kernel 2: ONE node per 128-thread block (grid 4096), ONE column per thread.
//   Lean registers (launch_bounds cap 56) -> ~36 warps/SM occupancy cap.
//   cv (C-table) loads perfectly coalesced (consecutive j), double-buffered
//   across 8-k chunks; E staged via cp.async; e-row consumed in two halves
//   to keep peak live registers low.
// ---------------------------------------------------------------------------
__global__ void __launch_bounds__(128, 9) edge_max_kernel(
    const float* __restrict__ eattr,  // [4,1024,1024,16]
    const float* __restrict__ W,      // [144,128]
    const int*   __restrict__ dst,    // [131072]
    float*       __restrict__ out)    // [4096,128]
{
    const int n = blockIdx.x;
    const int j = threadIdx.x;        // column 0..127

    __shared__ int sd[KNBR];
    __shared__ __align__(16) float se[KNBR][EPAD];   // 2.5 KB

    if (j < KNBR) sd[j] = dst[n * KNBR + j];
    __syncthreads();

    // stage E rows: 128 16B-chunks, one per thread
    {
        const int ck = j >> 2, cq = j & 3;
        const int ui = sd[ck] & (VDIM - 1);
        cp_async16(smem_u32(&se[ck][cq * 4]),
                   eattr + ((size_t)n * VDIM + ui) * EDIM + cq * 4);
        asm volatile("cp.async.commit_group;");
    }

    // W3 column j as 8 packed (t, t+1) pairs (16 regs); flies during gather
    uint64_t w3[8];
#pragma unroll
    for (int p = 0; p < 8; p++) {
        w3[p] = pack_f32x2(W[(2 * CDIM + 2 * p) * OUTD + j],
                           W[(2 * CDIM + 2 * p + 1) * OUTD + j]);
    }
    const float av = g_A[n * OUTD + j];

    asm volatile("cp.async.wait_group 0;");
    __syncthreads();

    const uint32_t se_base = smem_u32(&se[0][0]);
    float best = -1e30f;

    // C-table chunk 0: coalesced LDG.32 (consecutive j -> 512B/row)
    float cv[8];
#pragma unroll
    for (int u = 0; u < 8; u++) cv[u] = g_C[sd[u] * OUTD + j];

#pragma unroll
    for (int kb = 0; kb < KNBR; kb += 8) {
        // prefetch next chunk's C values (overlaps the FMA work below)
        float cvn[8];
        if (kb + 8 < KNBR) {
#pragma unroll
            for (int u = 0; u < 8; u++) cvn[u] = g_C[sd[kb + 8 + u] * OUTD + j];
        }

#pragma unroll
        for (int u = 0; u < 8; u++) {
            const uint32_t row = se_base + (kb + u) * (EPAD * 4);
            uint64_t acc = pack_f32x2(cv[u], 0.0f);

            // first half of the e-row (8 floats), then second half: peak 4 u64 live
            {
                uint64_t e0, e1, e2, e3;
                lds_v2_u64(e0, e1, row);
                lds_v2_u64(e2, e3, row + 16);
                acc = fma_f32x2(e0, w3[0], acc);
                acc = fma_f32x2(e1, w3[1], acc);
                acc = fma_f32x2(e2, w3[2], acc);
                acc = fma_f32x2(e3, w3[3], acc);
            }
            {
                uint64_t e4, e5, e6, e7;
                lds_v2_u64(e4, e5, row + 32);
                lds_v2_u64(e6, e7, row + 48);
                acc = fma_f32x2(e4, w3[4], acc);
                acc = fma_f32x2(e5, w3[5], acc);
                acc = fma_f32x2(e6, w3[6], acc);
                acc = fma_f32x2(e7, w3[7], acc);
            }

            float lo, hi;
            unpack_f32x2(lo, hi, acc);
            best = fmaxf(best, lo + hi);
        }

#pragma unroll
        for (int u = 0; u < 8; u++) cv[u] = cvn[u];
    }

    out[n * OUTD + j] = fmaxf(av + best, 0.0f);
}

// ---------------------------------------------------------------------------
// Inputs: 0 node_features [4,1024,64] f32 | 1 edge_attributes [4,1024,1024,16] f32
//         2 W [144,128] f32 | 3 b [128] f32 | 4 src i32 (unused) | 5 dst i32
// Output: f32 [4,1024,128]
// ---------------------------------------------------------------------------
extern "C" void kernel_launch(void* const* d_in, const int* in_sizes, int n_in,
                              void* d_out, int out_size)
{
    const float* x     = (const float*)d_in[0];
    const float* eattr = (const float*)d_in[1];
    const float* W     = (const float*)d_in[2];
    const float* bias  = (const float*)d_in[3];
    const int*   dst   = (const int*)d_in[5];
    float*       out   = (float*)d_out;

    node_tables_kernel<<<NODES / NT_NODES, 128>>>(x, W, bias);
    edge_max_kernel<<<NODES, 128>>>(eattr, W, dst, out);
}

// round 12
// speedup vs baseline: 1.1164x; 1.1164x over previous
#include <cuda_runtime.h>
#include <cuda_bf16.h>
#include <cstdint>

// EdgeConvE: B=4, V=1024, C=64, E=16, K=32, OUT=128, NODES=4096, EDGES=131072
// src = repeat(arange(4096), 32) (structural) => segment n = edges [n*32,(n+1)*32)
// dst & 1023 = local neighbor (block-diagonal graphs).
//
// Algebra: feat@W = x_s@(W1-W2) + x_d@W2 + e@W3
//   A[n] = x_n@(W1-W2)+b ; C[n] = x_n@W2
//   out[n][j] = max(0, A[n][j] + max_k( C[dst_k][j] + e_k . W3[:,j] ))

#define NODES 4096
#define VDIM  1024
#define CDIM  64
#define EDIM  16
#define KNBR  32
#define OUTD  128
#define EPAD  20     // E smem row stride in floats (bank-conflict-free)

__device__ float g_A[NODES * OUTD];
__device__ float g_C[NODES * OUTD];

// ---------------- f32x2 helpers ----------------
__device__ __forceinline__ uint64_t pack_f32x2(float lo, float hi) {
    uint64_t r;
    asm("mov.b64 %0, {%1, %2};" : "=l"(r) : "f"(lo), "f"(hi));
    return r;
}
__device__ __forceinline__ void unpack_f32x2(float& lo, float& hi, uint64_t v) {
    asm("mov.b64 {%0, %1}, %2;" : "=f"(lo), "=f"(hi) : "l"(v));
}
__device__ __forceinline__ uint64_t fma_f32x2(uint64_t a, uint64_t b, uint64_t c) {
    uint64_t d;
    asm("fma.rn.f32x2 %0, %1, %2, %3;" : "=l"(d) : "l"(a), "l"(b), "l"(c));
    return d;
}
__device__ __forceinline__ void lds_v2_u64(uint64_t& a, uint64_t& b, uint32_t addr) {
    asm("ld.shared.v2.u64 {%0, %1}, [%2];" : "=l"(a), "=l"(b) : "r"(addr));
}
__device__ __forceinline__ uint64_t lds_u64(uint32_t addr) {
    uint64_t a;
    asm("ld.shared.u64 %0, [%1];" : "=l"(a) : "r"(addr));
    return a;
}
__device__ __forceinline__ uint32_t smem_u32(const void* p) {
    return (uint32_t)__cvta_generic_to_shared(p);
}
__device__ __forceinline__ void cp_async16(uint32_t s, const void* g) {
    asm volatile("cp.async.cg.shared.global [%0], [%1], 16;" :: "r"(s), "l"(g));
}

// ---------------------------------------------------------------------------
// Kernel 1: per-node linear tables (f32x2-packed over node pairs). grid 1024.
// ---------------------------------------------------------------------------
#define NT_NODES 4
__global__ void __launch_bounds__(128) node_tables_kernel(
    const float* __restrict__ x, const float* __restrict__ W,
    const float* __restrict__ bias)
{
    __shared__ float xs[CDIM][NT_NODES];
    const int j  = threadIdx.x;
    const int n0 = blockIdx.x * NT_NODES;

    for (int it = 0; it < NT_NODES * CDIM / 128; it++) {
        int idx = j + it * 128;
        xs[idx & 63][idx >> 6] = x[n0 * CDIM + idx];
    }
    __syncthreads();

    const float bj = bias[j];
    uint64_t accA[NT_NODES / 2], accC[NT_NODES / 2];
#pragma unroll
    for (int p = 0; p < NT_NODES / 2; p++) {
        accA[p] = pack_f32x2(bj, bj);
        accC[p] = pack_f32x2(0.0f, 0.0f);
    }
    const uint32_t xs_base = smem_u32(&xs[0][0]);

#pragma unroll 8
    for (int c = 0; c < CDIM; c++) {
        const float w1 = W[c * OUTD + j];
        const float w2 = W[(CDIM + c) * OUTD + j];
        const uint64_t wd2 = pack_f32x2(w1 - w2, w1 - w2);
        const uint64_t w22 = pack_f32x2(w2, w2);
        const uint32_t rowa = xs_base + c * (NT_NODES * 4);
#pragma unroll
        for (int p = 0; p < NT_NODES / 2; p++) {
            uint64_t xv2 = lds_u64(rowa + p * 8);
            accA[p] = fma_f32x2(xv2, wd2, accA[p]);
            accC[p] = fma_f32x2(xv2, w22, accC[p]);
        }
    }
#pragma unroll
    for (int p = 0; p < NT_NODES / 2; p++) {
        float a0, a1, c0, c1;
        unpack_f32x2(a0, a1, accA[p]);
        unpack_f32x2(c0, c1, accC[p]);
        g_A[(n0 + 2 * p) * OUTD + j]     = a0;
        g_A[(n0 + 2 * p + 1) * OUTD + j] = a1;
        g_C[(n0 + 2 * p) * OUTD + j]     = c0;
        g_C[(n0 + 2 * p + 1) * OUTD + j] = c1;
    }
}

// ---------------------------------------------------------------------------
// Kernel 2: R6 structure, lean registers.
//   ONE node per 64-thread block (grid 4096); thread t owns cols (2t, 2t+1).
//   Regs capped at 56 (launch_bounds 64,18 -> 36 warps/SM cap): cv chunks of
//   4, e-row consumed in two 4-reg halves. Latency hidden by occupancy.
// ---------------------------------------------------------------------------
__global__ void __launch_bounds__(64, 18) edge_max_kernel(
    const float* __restrict__ eattr,  // [4,1024,1024,16]
    const float* __restrict__ W,      // [144,128]
    const int*   __restrict__ dst,    // [131072]
    float*       __restrict__ out)    // [4096,128]
{
    const int n  = blockIdx.x;
    const int t  = threadIdx.x;       // 0..63
    const int j0 = t * 2;

    __shared__ int sd[KNBR];
    __shared__ __align__(16) float se[KNBR][EPAD];   // 2.5 KB

    if (t < KNBR) sd[t] = dst[n * KNBR + t];
    __syncthreads();

    // stage E rows: 128 16B-chunks, 2 per thread
#pragma unroll
    for (int half = 0; half < 2; half++) {
        const int c  = t + half * 64;
        const int ck = c >> 2;
        const int cq = c & 3;
        const int ui = sd[ck] & (VDIM - 1);
        cp_async16(smem_u32(&se[ck][cq * 4]),
                   eattr + ((size_t)n * VDIM + ui) * EDIM + cq * 4);
    }
    asm volatile("cp.async.commit_group;");

    // W3 t-pair columns for cols j0, j0+1 (32 regs; LDGs fly during gather)
    uint64_t w3a[8], w3b[8];
#pragma unroll
    for (int p = 0; p < 8; p++) {
        w3a[p] = pack_f32x2(W[(2 * CDIM + 2 * p) * OUTD + j0],
                            W[(2 * CDIM + 2 * p + 1) * OUTD + j0]);
        w3b[p] = pack_f32x2(W[(2 * CDIM + 2 * p) * OUTD + j0 + 1],
                            W[(2 * CDIM + 2 * p + 1) * OUTD + j0 + 1]);
    }
    const float2 av = *reinterpret_cast<const float2*>(g_A + n * OUTD + j0);

    asm volatile("cp.async.wait_group 0;");
    __syncthreads();

    const uint32_t se_base = smem_u32(&se[0][0]);
    float best0 = -1e30f, best1 = -1e30f;

#pragma unroll
    for (int kb = 0; kb < KNBR; kb += 4) {
        // C-table rows for this 4-chunk (coalesced float2 LDGs, L2-resident)
        float2 cv[4];
#pragma unroll
        for (int u = 0; u < 4; u++)
            cv[u] = *reinterpret_cast<const float2*>(g_C + sd[kb + u] * OUTD + j0);

#pragma unroll
        for (int u = 0; u < 4; u++) {
            const uint32_t row = se_base + (kb + u) * (EPAD * 4);
            uint64_t a0 = pack_f32x2(cv[u].x, 0.0f);
            uint64_t a1 = pack_f32x2(cv[u].y, 0.0f);

            // e-row in two 4-register halves (peak 4 u64 live)
            {
                uint64_t e0, e1, e2, e3;
                lds_v2_u64(e0, e1, row);
                lds_v2_u64(e2, e3, row + 16);
                a0 = fma_f32x2(e0, w3a[0], a0);  a1 = fma_f32x2(e0, w3b[0], a1);
                a0 = fma_f32x2(e1, w3a[1], a0);  a1 = fma_f32x2(e1, w3b[1], a1);
                a0 = fma_f32x2(e2, w3a[2], a0);  a1 = fma_f32x2(e2, w3b[2], a1);
                a0 = fma_f32x2(e3, w3a[3], a0);  a1 = fma_f32x2(e3, w3b[3], a1);
            }
            {
                uint64_t e4, e5, e6, e7;
                lds_v2_u64(e4, e5, row + 32);
                lds_v2_u64(e6, e7, row + 48);
                a0 = fma_f32x2(e4, w3a[4], a0);  a1 = fma_f32x2(e4, w3b[4], a1);
                a0 = fma_f32x2(e5, w3a[5], a0);  a1 = fma_f32x2(e5, w3b[5], a1);
                a0 = fma_f32x2(e6, w3a[6], a0);  a1 = fma_f32x2(e6, w3b[6], a1);
                a0 = fma_f32x2(e7, w3a[7], a0);  a1 = fma_f32x2(e7, w3b[7], a1);
            }

            float lo0, hi0, lo1, hi1;
            unpack_f32x2(lo0, hi0, a0);
            unpack_f32x2(lo1, hi1, a1);
            best0 = fmaxf(best0, lo0 + hi0);
            best1 = fmaxf(best1, lo1 + hi1);
        }
    }

    float r0 = fmaxf(av.x + best0, 0.0f);
    float r1 = fmaxf(av.y + best1, 0.0f);
    *reinterpret_cast<float2*>(out + n * OUTD + j0) = make_float2(r0, r1);
}

// ---------------------------------------------------------------------------
// Inputs: 0 node_features [4,1024,64] f32 | 1 edge_attributes [4,1024,1024,16] f32
//         2 W [144,128] f32 | 3 b [128] f32 | 4 src i32 (unused) | 5 dst i32
// Output: f32 [4,1024,128]
// ---------------------------------------------------------------------------
extern "C" void kernel_launch(void* const* d_in, const int* in_sizes, int n_in,
                              void* d_out, int out_size)
{
    const float* x     = (const float*)d_in[0];
    const float* eattr = (const float*)d_in[1];
    const float* W     = (const float*)d_in[2];
    const float* bias  = (const float*)d_in[3];
    const int*   dst   = (const int*)d_in[5];
    float*       out   = (float*)d_out;

    node_tables_kernel<<<NODES / NT_NODES, 128>>>(x, W, bias);
    edge_max_kernel<<<NODES, 64>>>(eattr, W, dst, out);
}

// round 13
// speedup vs baseline: 1.2099x; 1.0837x over previous
#include <cuda_runtime.h>
#include <cuda_bf16.h>
#include <cstdint>

// EdgeConvE: B=4, V=1024, C=64, E=16, K=32, OUT=128, NODES=4096, EDGES=131072
// src = repeat(arange(4096), 32) (structural) => segment n = edges [n*32,(n+1)*32)
// dst & 1023 = local neighbor (block-diagonal graphs).
//
// Algebra: feat@W = x_s@(W1-W2) + x_d@W2 + e@W3
//   A[n] = x_n@(W1-W2)+b ; C[n] = x_n@W2
//   out[n][j] = max(0, A[n][j] + max_k( C[dst_k][j] + e_k . W3[:,j] ))
//
// This round: PDL (programmatic dependent launch) — the edge kernel starts
// while node_tables runs; its input-only prologue (dst load, E cp.async
// gather, W3 loads) overlaps node_tables; cudaGridDependencySynchronize()
// guards the first g_A/g_C read.

#define NODES 4096
#define VDIM  1024
#define CDIM  64
#define EDIM  16
#define KNBR  32
#define OUTD  128
#define EPAD  20     // E smem row stride in floats (bank-conflict-free)

__device__ float g_A[NODES * OUTD];
__device__ float g_C[NODES * OUTD];

// ---------------- f32x2 helpers ----------------
__device__ __forceinline__ uint64_t pack_f32x2(float lo, float hi) {
    uint64_t r;
    asm("mov.b64 %0, {%1, %2};" : "=l"(r) : "f"(lo), "f"(hi));
    return r;
}
__device__ __forceinline__ void unpack_f32x2(float& lo, float& hi, uint64_t v) {
    asm("mov.b64 {%0, %1}, %2;" : "=f"(lo), "=f"(hi) : "l"(v));
}
__device__ __forceinline__ uint64_t fma_f32x2(uint64_t a, uint64_t b, uint64_t c) {
    uint64_t d;
    asm("fma.rn.f32x2 %0, %1, %2, %3;" : "=l"(d) : "l"(a), "l"(b), "l"(c));
    return d;
}
__device__ __forceinline__ void lds_v2_u64(uint64_t& a, uint64_t& b, uint32_t addr) {
    asm("ld.shared.v2.u64 {%0, %1}, [%2];" : "=l"(a), "=l"(b) : "r"(addr));
}
__device__ __forceinline__ uint64_t lds_u64(uint32_t addr) {
    uint64_t a;
    asm("ld.shared.u64 %0, [%1];" : "=l"(a) : "r"(addr));
    return a;
}
__device__ __forceinline__ uint32_t smem_u32(const void* p) {
    return (uint32_t)__cvta_generic_to_shared(p);
}
__device__ __forceinline__ void cp_async16(uint32_t s, const void* g) {
    asm volatile("cp.async.cg.shared.global [%0], [%1], 16;" :: "r"(s), "l"(g));
}

// ---------------------------------------------------------------------------
// Kernel 1: per-node linear tables (f32x2-packed over node pairs). grid 1024.
// Triggers the dependent edge kernel's launch at entry (PDL).
// ---------------------------------------------------------------------------
#define NT_NODES 4
__global__ void __launch_bounds__(128) node_tables_kernel(
    const float* __restrict__ x, const float* __restrict__ W,
    const float* __restrict__ bias)
{
    // Fire the dependent launch immediately: edge kernel's prologue
    // (gathers of inputs) overlaps this kernel's execution.
    cudaTriggerProgrammaticLaunchCompletion();

    __shared__ float xs[CDIM][NT_NODES];
    const int j  = threadIdx.x;
    const int n0 = blockIdx.x * NT_NODES;

    for (int it = 0; it < NT_NODES * CDIM / 128; it++) {
        int idx = j + it * 128;
        xs[idx & 63][idx >> 6] = x[n0 * CDIM + idx];
    }
    __syncthreads();

    const float bj = bias[j];
    uint64_t accA[NT_NODES / 2], accC[NT_NODES / 2];
#pragma unroll
    for (int p = 0; p < NT_NODES / 2; p++) {
        accA[p] = pack_f32x2(bj, bj);
        accC[p] = pack_f32x2(0.0f, 0.0f);
    }
    const uint32_t xs_base = smem_u32(&xs[0][0]);

#pragma unroll 8
    for (int c = 0; c < CDIM; c++) {
        const float w1 = W[c * OUTD + j];
        const float w2 = W[(CDIM + c) * OUTD + j];
        const uint64_t wd2 = pack_f32x2(w1 - w2, w1 - w2);
        const uint64_t w22 = pack_f32x2(w2, w2);
        const uint32_t rowa = xs_base + c * (NT_NODES * 4);
#pragma unroll
        for (int p = 0; p < NT_NODES / 2; p++) {
            uint64_t xv2 = lds_u64(rowa + p * 8);
            accA[p] = fma_f32x2(xv2, wd2, accA[p]);
            accC[p] = fma_f32x2(xv2, w22, accC[p]);
        }
    }
#pragma unroll
    for (int p = 0; p < NT_NODES / 2; p++) {
        float a0, a1, c0, c1;
        unpack_f32x2(a0, a1, accA[p]);
        unpack_f32x2(c0, c1, accC[p]);
        g_A[(n0 + 2 * p) * OUTD + j]     = a0;
        g_A[(n0 + 2 * p + 1) * OUTD + j] = a1;
        g_C[(n0 + 2 * p) * OUTD + j]     = c0;
        g_C[(n0 + 2 * p + 1) * OUTD + j] = c1;
    }
}

// ---------------------------------------------------------------------------
// Kernel 2: the R6 champion (one node per 64-thread block), PDL-guarded.
//   Prologue reads only inputs (dst, eattr, W) -> runs concurrently with K1.
//   cudaGridDependencySynchronize() before the first g_A/g_C access.
// ---------------------------------------------------------------------------
__global__ void __launch_bounds__(64) edge_max_kernel(
    const float* __restrict__ eattr,  // [4,1024,1024,16]
    const float* __restrict__ W,      // [144,128]
    const int*   __restrict__ dst,    // [131072]
    float*       __restrict__ out)    // [4096,128]
{
    const int n  = blockIdx.x;
    const int t  = threadIdx.x;       // 0..63
    const int j0 = t * 2;

    __shared__ int sd[KNBR];
    __shared__ __align__(16) float se[KNBR][EPAD];   // 2.5 KB

    if (t < KNBR) sd[t] = dst[n * KNBR + t];
    __syncthreads();

    // stage E rows: 128 16B-chunks, 2 per thread (input-only; overlaps K1)
#pragma unroll
    for (int half = 0; half < 2; half++) {
        const int c  = t + half * 64;
        const int ck = c >> 2;
        const int cq = c & 3;
        const int ui = sd[ck] & (VDIM - 1);
        cp_async16(smem_u32(&se[ck][cq * 4]),
                   eattr + ((size_t)n * VDIM + ui) * EDIM + cq * 4);
    }
    asm volatile("cp.async.commit_group;");

    // W3 t-pair columns for cols j0, j0+1 (input-only; overlaps K1 + gather)
    uint64_t w3a[8], w3b[8];
#pragma unroll
    for (int p = 0; p < 8; p++) {
        w3a[p] = pack_f32x2(W[(2 * CDIM + 2 * p) * OUTD + j0],
                            W[(2 * CDIM + 2 * p + 1) * OUTD + j0]);
        w3b[p] = pack_f32x2(W[(2 * CDIM + 2 * p) * OUTD + j0 + 1],
                            W[(2 * CDIM + 2 * p + 1) * OUTD + j0 + 1]);
    }

    // ---- wait for node_tables' g_A/g_C to be visible ----
    cudaGridDependencySynchronize();

    const float2 av = *reinterpret_cast<const float2*>(g_A + n * OUTD + j0);

    asm volatile("cp.async.wait_group 0;");
    __syncthreads();

    const uint32_t se_base = smem_u32(&se[0][0]);
    float best0 = -1e30f, best1 = -1e30f;

#pragma unroll
    for (int kb = 0; kb < KNBR; kb += 8) {
        // C-table rows for this chunk (L2-resident)
        float2 cv[8];
#pragma unroll
        for (int u = 0; u < 8; u++)
            cv[u] = *reinterpret_cast<const float2*>(g_C + sd[kb + u] * OUTD + j0);

#pragma unroll
        for (int u = 0; u < 8; u++) {
            const uint32_t row = se_base + (kb + u) * (EPAD * 4);
            uint64_t e0, e1, e2, e3, e4, e5, e6, e7;
            lds_v2_u64(e0, e1, row);
            lds_v2_u64(e2, e3, row + 16);
            lds_v2_u64(e4, e5, row + 32);
            lds_v2_u64(e6, e7, row + 48);

            uint64_t a0 = pack_f32x2(cv[u].x, 0.0f);
            uint64_t a1 = pack_f32x2(cv[u].y, 0.0f);
            a0 = fma_f32x2(e0, w3a[0], a0);  a1 = fma_f32x2(e0, w3b[0], a1);
            a0 = fma_f32x2(e1, w3a[1], a0);  a1 = fma_f32x2(e1, w3b[1], a1);
            a0 = fma_f32x2(e2, w3a[2], a0);  a1 = fma_f32x2(e2, w3b[2], a1);
            a0 = fma_f32x2(e3, w3a[3], a0);  a1 = fma_f32x2(e3, w3b[3], a1);
            a0 = fma_f32x2(e4, w3a[4], a0);  a1 = fma_f32x2(e4, w3b[4], a1);
            a0 = fma_f32x2(e5, w3a[5], a0);  a1 = fma_f32x2(e5, w3b[5], a1);
            a0 = fma_f32x2(e6, w3a[6], a0);  a1 = fma_f32x2(e6, w3b[6], a1);
            a0 = fma_f32x2(e7, w3a[7], a0);  a1 = fma_f32x2(e7, w3b[7], a1);

            float lo0, hi0, lo1, hi1;
            unpack_f32x2(lo0, hi0, a0);
            unpack_f32x2(lo1, hi1, a1);
            best0 = fmaxf(best0, lo0 + hi0);
            best1 = fmaxf(best1, lo1 + hi1);
        }
    }

    float r0 = fmaxf(av.x + best0, 0.0f);
    float r1 = fmaxf(av.y + best1, 0.0f);
    *reinterpret_cast<float2*>(out + n * OUTD + j0) = make_float2(r0, r1);
}

// ---------------------------------------------------------------------------
// Inputs: 0 node_features [4,1024,64] f32 | 1 edge_attributes [4,1024,1024,16] f32
//         2 W [144,128] f32 | 3 b [128] f32 | 4 src i32 (unused) | 5 dst i32
// Output: f32 [4,1024,128]
// ---------------------------------------------------------------------------
extern "C" void kernel_launch(void* const* d_in, const int* in_sizes, int n_in,
                              void* d_out, int out_size)
{
    const float* x     = (const float*)d_in[0];
    const float* eattr = (const float*)d_in[1];
    const float* W     = (const float*)d_in[2];
    const float* bias  = (const float*)d_in[3];
    const int*   dst   = (const int*)d_in[5];
    float*       out   = (float*)d_out;

    node_tables_kernel<<<NODES / NT_NODES, 128>>>(x, W, bias);

    // PDL launch: edge kernel may start as soon as node_tables triggers;
    // its gridDependencySynchronize() guards the g_A/g_C reads.
    cudaLaunchConfig_t cfg = {};
    cfg.gridDim  = dim3(NODES);
    cfg.blockDim = dim3(64);
    cudaLaunchAttribute attrs[1];
    attrs[0].id = cudaLaunchAttributeProgrammaticStreamSerialization;
    attrs[0].val.programmaticStreamSerializationAllowed = 1;
    cfg.attrs = attrs;
    cfg.numAttrs = 1;
    cudaLaunchKernelEx(&cfg, edge_max_kernel, eattr, W, dst, out);
}